// round 12
// baseline (speedup 1.0000x reference)
#include <cuda_runtime.h>
#include <cuda_fp16.h>
#include <cstdint>

#define D_    1024
#define DFF_  4096
#define B_    4
#define S_    2048
#define BS_   (B_ * S_)        // 8192 rows
#define EPS_  1e-6f
#define SLOPE_ 0.01f

// ---------------- scratch (device globals; no allocation allowed) ----------------
__device__ __half g_xr  [BS_ * D_];                 // rounded X (QKV A-operand)
__device__ __half g_qkv [(long long)BS_ * 3 * D_];  // fused QKV output [8192, 3072]
__device__ __half g_vt  [BS_ * D_];                 // V^T per batch [D,S]
__device__ float  g_sc  [(long long)B_ * S_ * S_];  // scores (fp32)
__device__ __half g_attn[(long long)B_ * S_ * S_];  // softmax+intensity (fp16)
__device__ __half g_ao  [BS_ * D_];
__device__ float  g_h   [BS_ * D_];
__device__ __half g_hr  [BS_ * D_];                 // rounded h (FFN1 A-operand)
__device__ __half g_mid [(long long)BS_ * DFF_];
__device__ float  g_tmp [BS_ * D_];                 // O-proj out / FFN2 out
__device__ __half g_wqkv[3 * D_ * D_];              // [3072, 1024] transposed fp16
__device__ __half g_wto [D_ * D_];
__device__ __half g_wt1 [(long long)D_ * DFF_];     // W1^T : [DFF, D]
__device__ __half g_wt2 [(long long)D_ * DFF_];     // W2^T : [D, DFF]
__device__ float  g_bqkv[3 * D_];                   // concat bias (fp32)

// ---------------- PTX helpers (portable ISA only) ----------------
__device__ __forceinline__ uint32_t smem_to_u32(const void* smem_ptr) {
    uint32_t addr;
    asm("{ .reg .u64 tmp; cvta.to.shared.u64 tmp, %1; cvt.u32.u64 %0, tmp; }"
        : "=r"(addr) : "l"(smem_ptr));
    return addr;
}

#define CP_ASYNC16(saddr, gptr) \
    asm volatile("cp.async.cg.shared.global [%0], [%1], 16;" :: "r"(saddr), "l"(gptr))
#define CP_COMMIT() asm volatile("cp.async.commit_group;" ::: "memory")
#define CP_WAIT(n)  asm volatile("cp.async.wait_group %0;" :: "n"(n) : "memory")

#define LDSM_X4(r0, r1, r2, r3, addr) \
    asm volatile("ldmatrix.sync.aligned.m8n8.x4.shared.b16 {%0,%1,%2,%3}, [%4];" \
        : "=r"(r0), "=r"(r1), "=r"(r2), "=r"(r3) : "r"(addr))

__device__ __forceinline__ void mma_fp16(float* c, const uint32_t* a, const uint32_t* b) {
    asm volatile(
        "mma.sync.aligned.m16n8k16.row.col.f32.f16.f16.f32 "
        "{%0,%1,%2,%3}, {%4,%5,%6,%7}, {%8,%9}, {%0,%1,%2,%3};"
        : "+f"(c[0]), "+f"(c[1]), "+f"(c[2]), "+f"(c[3])
        : "r"(a[0]), "r"(a[1]), "r"(a[2]), "r"(a[3]), "r"(b[0]), "r"(b[1]));
}

// ---------------- block reductions ----------------
__device__ __forceinline__ float warpRedMax(float v) {
    #pragma unroll
    for (int o = 16; o > 0; o >>= 1) v = fmaxf(v, __shfl_xor_sync(0xffffffffu, v, o));
    return v;
}
__device__ __forceinline__ float warpRedSum(float v) {
    #pragma unroll
    for (int o = 16; o > 0; o >>= 1) v += __shfl_xor_sync(0xffffffffu, v, o);
    return v;
}
__device__ float blockRedMax(float v) {
    __shared__ float sh[8];
    int lane = threadIdx.x & 31, wid = threadIdx.x >> 5;
    __syncthreads();
    v = warpRedMax(v);
    if (lane == 0) sh[wid] = v;
    __syncthreads();
    float r = sh[0];
    #pragma unroll
    for (int i = 1; i < 8; i++) r = fmaxf(r, sh[i]);
    return r;
}
__device__ float blockRedSum(float v) {
    __shared__ float sh[8];
    int lane = threadIdx.x & 31, wid = threadIdx.x >> 5;
    __syncthreads();
    v = warpRedSum(v);
    if (lane == 0) sh[wid] = v;
    __syncthreads();
    float r = 0.f;
    #pragma unroll
    for (int i = 0; i < 8; i++) r += sh[i];
    return r;
}

// ================= persistent fp16 mma.sync GEMM (f32 accumulate) =================
// C[M,N](+z*sC) = act( alpha * A[M,K] @ Bt[N,K]^T + bias )
// 128x128 CTA tile, BK=64 halfs, 128 threads, 4 warps (2m x 2n), warp tile 64x64.
// 3-stage cp.async pipeline, SW128 swizzle, ldmatrix loads.
// Persistent: fixed grid, each CTA loops over tiles (kills wave quantization).
#define STAGES 3
#define TILE_BYTES  (128 * 128)               // 16 KB (128 rows x 128 bytes)
#define STAGE_BYTES (2 * TILE_BYTES)          // 32 KB
#define GEMM_DSMEM  (STAGES * STAGE_BYTES + 1024)

__device__ __forceinline__ void load_chunk64(
    uint32_t sA_base, uint32_t sB_base,
    const __half* __restrict__ gA, const __half* __restrict__ gB,
    int lda, int ldb, int tid)
{
    #pragma unroll
    for (int j = 0; j < 8; j++) {
        int idx = j * 128 + tid;          // 0..1023 : 16B segments of a 16KB tile
        int row = idx >> 3;
        int seg = idx & 7;
        uint32_t off = (uint32_t)idx * 16u;
        uint32_t sw = off ^ ((off >> 3) & 0x70u);
        const __half* ga = gA + row * lda + seg * 8;
        const __half* gb = gB + row * ldb + seg * 8;
        CP_ASYNC16(sA_base + sw, ga);
        CP_ASYNC16(sB_base + sw, gb);
    }
}

template<int ACT, int OUTH>
__global__ __launch_bounds__(128, 2)
void mma_gemm(const __half* __restrict__ A, const __half* __restrict__ Bt,
              const float* __restrict__ bias, void* __restrict__ Cv,
              int K, int lda, int ldb, int ldc,
              int sA, int sB, int sC, float alpha,
              int ntx, int nty, int ntz)
{
    extern __shared__ char smem_raw[];
    uint32_t smem_base = (smem_to_u32(smem_raw) + 1023u) & ~1023u;

    const int tid  = threadIdx.x;
    const int lane = tid & 31;
    const int wid  = tid >> 5;
    const int wm = wid >> 1;            // 0..1 : 64-row slab
    const int wn = wid & 1;             // 0..1 : 64-col slab
    const int NK = K >> 6;              // BK = 64 halfs
    const int ntile = ntx * nty * ntz;

    // ---- ldmatrix per-thread swizzled base byte offsets (tile-relative) ----
    const int g   = lane >> 3;
    const int rin = lane & 7;
    const int arow_off = ((g & 1) << 3) + rin;
    const int acol_b   = (g >> 1) << 4;
    uint32_t aswb[4];
    #pragma unroll
    for (int mf = 0; mf < 4; mf++) {
        int row = wm * 64 + mf * 16 + arow_off;
        uint32_t off = (uint32_t)row * 128u + (uint32_t)acol_b;
        aswb[mf] = off ^ (((uint32_t)row & 7u) << 4);
    }
    const int brow_off = ((g >> 1) << 3) + rin;
    const int bcol_b   = (g & 1) << 4;
    uint32_t bswb[4];
    #pragma unroll
    for (int p = 0; p < 4; p++) {
        int nrow = wn * 64 + p * 16 + brow_off;
        uint32_t off = (uint32_t)nrow * 128u + (uint32_t)bcol_b;
        bswb[p] = off ^ (((uint32_t)nrow & 7u) << 4);
    }

    for (int t = blockIdx.x; t < ntile; t += gridDim.x) {
        const int z   = t / (ntx * nty);
        const int rem = t - z * ntx * nty;
        const int bm  = (rem / ntx) * 128;
        const int bn  = (rem - (rem / ntx) * ntx) * 128;

        const __half* gA0 = A  + z * sA + bm * lda;
        const __half* gB0 = Bt + z * sB + bn * ldb;

        // drain previous tile's async groups; ensure no warp still reads smem
        CP_WAIT(0);
        __syncthreads();

        float c[4][8][4];
        #pragma unroll
        for (int i = 0; i < 4; i++)
            #pragma unroll
            for (int j = 0; j < 8; j++)
                #pragma unroll
                for (int r = 0; r < 4; r++) c[i][j][r] = 0.f;

        // prologue
        #pragma unroll
        for (int s = 0; s < STAGES - 1; s++) {
            uint32_t sa = smem_base + s * STAGE_BYTES;
            load_chunk64(sa, sa + TILE_BYTES, gA0 + s * 64, gB0 + s * 64, lda, ldb, tid);
            CP_COMMIT();
        }

        for (int kt = 0; kt < NK; kt++) {
            const int s = kt % STAGES;
            CP_WAIT(STAGES - 2);
            __syncthreads();

            const int ktn = kt + STAGES - 1;
            if (ktn < NK) {
                const int sn = ktn % STAGES;
                uint32_t sa = smem_base + sn * STAGE_BYTES;
                load_chunk64(sa, sa + TILE_BYTES, gA0 + ktn * 64, gB0 + ktn * 64,
                             lda, ldb, tid);
            }
            CP_COMMIT();

            const uint32_t sAb = smem_base + s * STAGE_BYTES;
            const uint32_t sBb = sAb + TILE_BYTES;
            #pragma unroll
            for (int ks = 0; ks < 4; ks++) {     // 4 x k16 = BK 64
                uint32_t a[4][4];
                uint32_t bb[4][4];
                #pragma unroll
                for (int mf = 0; mf < 4; mf++)
                    LDSM_X4(a[mf][0], a[mf][1], a[mf][2], a[mf][3], sAb + (aswb[mf] ^ (ks << 5)));
                #pragma unroll
                for (int p = 0; p < 4; p++)
                    LDSM_X4(bb[p][0], bb[p][1], bb[p][2], bb[p][3], sBb + (bswb[p] ^ (ks << 5)));
                #pragma unroll
                for (int mf = 0; mf < 4; mf++)
                    #pragma unroll
                    for (int nf = 0; nf < 8; nf++)
                        mma_fp16(c[mf][nf], a[mf], &bb[nf >> 1][(nf & 1) * 2]);
            }
        }

        // ---- epilogue ----
        float*  Cf = (float*)Cv  + sC * z;
        __half* Ch = (__half*)Cv + sC * z;
        const int r0base = bm + wm * 64 + (lane >> 2);
        const int c0base = bn + wn * 64 + (lane & 3) * 2;
        #pragma unroll
        for (int mf = 0; mf < 4; mf++) {
            #pragma unroll
            for (int nf = 0; nf < 8; nf++) {
                int col = c0base + nf * 8;
                float bx = 0.f, by = 0.f;
                if (bias != nullptr) { bx = bias[col]; by = bias[col + 1]; }
                #pragma unroll
                for (int half_ = 0; half_ < 2; half_++) {
                    int row = r0base + mf * 16 + half_ * 8;
                    float vx = c[mf][nf][half_ * 2 + 0] * alpha + bx;
                    float vy = c[mf][nf][half_ * 2 + 1] * alpha + by;
                    if (ACT == 1) {
                        vx = vx > 0.f ? vx : SLOPE_ * vx;
                        vy = vy > 0.f ? vy : SLOPE_ * vy;
                    }
                    if (OUTH == 1) {
                        *(__half2*)&Ch[row * ldc + col] = __floats2half2_rn(vx, vy);
                    } else {
                        *(float2*)&Cf[row * ldc + col] = make_float2(vx, vy);
                    }
                }
            }
        }
    }
}

// ================= fused prep kernel =================
#define P_X0   0
#define P_B0   8192
#define P_T30  8195
#define P_W10  11267
#define P_W20  15363
#define P_WO0  19459
#define PREP_BLOCKS 20483

__device__ __forceinline__ void tr_tile(const float* __restrict__ in, __half* __restrict__ out,
                                        int ldIn, int ldOut, int r0, int c0)
{
    __shared__ float t[32][33];
    const int tx = threadIdx.x & 31;
    const int ty = threadIdx.x >> 5;
    #pragma unroll
    for (int j = 0; j < 4; j++)
        t[ty + j * 8][tx] = in[(long long)(r0 + ty + j * 8) * ldIn + c0 + tx];
    __syncthreads();
    #pragma unroll
    for (int j = 0; j < 4; j++)
        out[(long long)(c0 + ty + j * 8) * ldOut + r0 + tx] = __float2half(t[tx][ty + j * 8]);
}

__global__ __launch_bounds__(256)
void prep_kernel(const float* __restrict__ X, __half* __restrict__ xr,
                 const float* __restrict__ bq, const float* __restrict__ bk,
                 const float* __restrict__ bv, float* __restrict__ bqkv,
                 const float* __restrict__ Wq, const float* __restrict__ Wk,
                 const float* __restrict__ Wv, __half* __restrict__ wqkv,
                 const float* __restrict__ W1, __half* __restrict__ wt1,
                 const float* __restrict__ W2, __half* __restrict__ wt2,
                 const float* __restrict__ Wo, __half* __restrict__ wto)
{
    const int b = blockIdx.x;
    if (b < P_B0) {
        int i = b * 256 + threadIdx.x;
        float4 v = ((const float4*)X)[i];
        __half2* o = (__half2*)(xr + 4 * (long long)i);
        o[0] = __floats2half2_rn(v.x, v.y);
        o[1] = __floats2half2_rn(v.z, v.w);
    } else if (b < P_T30) {
        int zz = b - P_B0;
        const float* src = (zz == 0) ? bq : (zz == 1) ? bk : bv;
        #pragma unroll
        for (int j = 0; j < 4; j++)
            bqkv[zz * D_ + threadIdx.x + j * 256] = src[threadIdx.x + j * 256];
    } else if (b < P_W10) {
        int id = b - P_T30;
        int z = id >> 10;            // 0..2
        int rem = id & 1023;
        const float* in = (z == 0) ? Wq : (z == 1) ? Wk : Wv;
        tr_tile(in, wqkv + (long long)z * D_ * D_, D_, D_,
                (rem >> 5) * 32, (rem & 31) * 32);
    } else if (b < P_W20) {
        int id = b - P_W10;          // W1 [D, DFF] -> wt1 [DFF, D]
        tr_tile(W1, wt1, DFF_, D_, (id >> 7) * 32, (id & 127) * 32);
    } else if (b < P_WO0) {
        int id = b - P_W20;          // W2 [DFF, D] -> wt2 [D, DFF]
        tr_tile(W2, wt2, D_, DFF_, (id >> 5) * 32, (id & 31) * 32);
    } else {
        int id = b - P_WO0;          // Wo [D, D] -> wto [D, D]
        tr_tile(Wo, wto, D_, D_, (id >> 5) * 32, (id & 31) * 32);
    }
}

// ---------------- half transpose (V -> V^T per batch), 64x64 tiles, half2 I/O ----------------
__global__ __launch_bounds__(256)
void transpose_h_kernel(const __half* __restrict__ in, __half* __restrict__ out,
                        int ldIn, int ldOut, long long sIn, long long sOut)
{
    __shared__ __half t[64][65];
    const int z = blockIdx.z;
    in  += (long long)z * sIn;
    out += (long long)z * sOut;
    const int c0 = blockIdx.x * 64;
    const int r0 = blockIdx.y * 64;
    const int tx = threadIdx.x & 31;      // half2 col 0..31
    const int ty = threadIdx.x >> 5;      // 0..7
    #pragma unroll
    for (int j = 0; j < 8; j++) {
        int row = ty + j * 8;
        __half2 v = *(const __half2*)&in[(long long)(r0 + row) * ldIn + c0 + 2 * tx];
        t[row][2 * tx]     = __low2half(v);
        t[row][2 * tx + 1] = __high2half(v);
    }
    __syncthreads();
    #pragma unroll
    for (int j = 0; j < 8; j++) {
        int orow = ty + j * 8;            // output row = source col
        __half2 o = __halves2half2(t[2 * tx][orow], t[2 * tx + 1][orow]);
        *(__half2*)&out[(long long)(c0 + orow) * ldOut + r0 + 2 * tx] = o;
    }
}

// ---------------- softmax over last dim (S) + intensity add -> fp16 (vectorized) ----------------
__global__ __launch_bounds__(256)
void softmax_bias_kernel(const float* __restrict__ sc, const float* __restrict__ inten,
                         __half* __restrict__ out)
{
    long long row = blockIdx.x;
    const float4* s4 = (const float4*)(sc    + row * (long long)S_);
    const float4* i4 = (const float4*)(inten + row * (long long)S_);
    __half2*     o2  = (__half2*)     (out   + row * (long long)S_);
    int tid = threadIdx.x;

    float4 va = s4[tid];
    float4 vb = s4[tid + 256];
    float m = fmaxf(fmaxf(fmaxf(va.x, va.y), fmaxf(va.z, va.w)),
                    fmaxf(fmaxf(vb.x, vb.y), fmaxf(vb.z, vb.w)));
    m = blockRedMax(m);

    va.x = __expf(va.x - m); va.y = __expf(va.y - m);
    va.z = __expf(va.z - m); va.w = __expf(va.w - m);
    vb.x = __expf(vb.x - m); vb.y = __expf(vb.y - m);
    vb.z = __expf(vb.z - m); vb.w = __expf(vb.w - m);
    float sum = (va.x + va.y + va.z + va.w) + (vb.x + vb.y + vb.z + vb.w);
    sum = blockRedSum(sum);
    float inv = 1.f / sum;

    float4 ia = i4[tid];
    float4 ib = i4[tid + 256];
    o2[2 * tid]       = __floats2half2_rn(fmaf(va.x, inv, ia.x), fmaf(va.y, inv, ia.y));
    o2[2 * tid + 1]   = __floats2half2_rn(fmaf(va.z, inv, ia.z), fmaf(va.w, inv, ia.w));
    o2[512 + 2 * tid]     = __floats2half2_rn(fmaf(vb.x, inv, ib.x), fmaf(vb.y, inv, ib.y));
    o2[512 + 2 * tid + 1] = __floats2half2_rn(fmaf(vb.z, inv, ib.z), fmaf(vb.w, inv, ib.w));
}

// ---------------- residual + layernorm (optionally also writes fp16 copy) ----------------
template<int WR>
__global__ __launch_bounds__(256)
void residual_ln_kernel(const float* __restrict__ a, const float* __restrict__ b,
                        const float* __restrict__ g, const float* __restrict__ be,
                        float* __restrict__ out, __half* __restrict__ outr)
{
    long long row = blockIdx.x;
    int tid = threadIdx.x;
    const float4* pa = (const float4*)(a + row * (long long)D_);
    const float4* pb = (const float4*)(b + row * (long long)D_);
    float4 x = pa[tid];
    float4 y = pb[tid];
    x.x += y.x; x.y += y.y; x.z += y.z; x.w += y.w;

    float s  = x.x + x.y + x.z + x.w;
    float ss = x.x * x.x + x.y * x.y + x.z * x.z + x.w * x.w;
    s  = blockRedSum(s);
    ss = blockRedSum(ss);
    float mu  = s * (1.f / D_);
    float var = ss * (1.f / D_) - mu * mu;
    float r   = rsqrtf(var + EPS_);

    float4 gg = ((const float4*)g)[tid];
    float4 bb = ((const float4*)be)[tid];
    float4 o;
    o.x = (x.x - mu) * r * gg.x + bb.x;
    o.y = (x.y - mu) * r * gg.y + bb.y;
    o.z = (x.z - mu) * r * gg.z + bb.z;
    o.w = (x.w - mu) * r * gg.w + bb.w;
    ((float4*)(out + row * (long long)D_))[tid] = o;
    if (WR) {
        __half2* po = (__half2*)(outr + row * (long long)D_ + 4 * tid);
        po[0] = __floats2half2_rn(o.x, o.y);
        po[1] = __floats2half2_rn(o.z, o.w);
    }
}

// ---------------- launcher ----------------
extern "C" void kernel_launch(void* const* d_in, const int* in_sizes, int n_in,
                              void* d_out, int out_size)
{
    const float* X     = (const float*)d_in[0];
    const float* inten = (const float*)d_in[1];
    const float* Wq = (const float*)d_in[2];  const float* bq = (const float*)d_in[3];
    const float* Wk = (const float*)d_in[4];  const float* bk = (const float*)d_in[5];
    const float* Wv = (const float*)d_in[6];  const float* bv = (const float*)d_in[7];
    const float* Wo = (const float*)d_in[8];  const float* bo = (const float*)d_in[9];
    const float* W1 = (const float*)d_in[10]; const float* b1 = (const float*)d_in[11];
    const float* W2 = (const float*)d_in[12]; const float* b2 = (const float*)d_in[13];
    const float* g1 = (const float*)d_in[14]; const float* be1 = (const float*)d_in[15];
    const float* g2 = (const float*)d_in[16]; const float* be2 = (const float*)d_in[17];
    float* out = (float*)d_out;

    __half *xr, *qkv, *vt, *attn, *ao, *hr, *mid;
    __half *wqkv, *wto, *wt1, *wt2;
    float *sc, *h, *tmp, *bqkv;
    cudaGetSymbolAddress((void**)&xr,   g_xr);
    cudaGetSymbolAddress((void**)&qkv,  g_qkv);
    cudaGetSymbolAddress((void**)&vt,   g_vt);
    cudaGetSymbolAddress((void**)&sc,   g_sc);
    cudaGetSymbolAddress((void**)&attn, g_attn);
    cudaGetSymbolAddress((void**)&ao,   g_ao);
    cudaGetSymbolAddress((void**)&h,    g_h);
    cudaGetSymbolAddress((void**)&hr,   g_hr);
    cudaGetSymbolAddress((void**)&mid,  g_mid);
    cudaGetSymbolAddress((void**)&tmp,  g_tmp);
    cudaGetSymbolAddress((void**)&wqkv, g_wqkv);
    cudaGetSymbolAddress((void**)&wto,  g_wto);
    cudaGetSymbolAddress((void**)&wt1,  g_wt1);
    cudaGetSymbolAddress((void**)&wt2,  g_wt2);
    cudaGetSymbolAddress((void**)&bqkv, g_bqkv);

    cudaFuncSetAttribute(mma_gemm<0,0>, cudaFuncAttributeMaxDynamicSharedMemorySize, GEMM_DSMEM);
    cudaFuncSetAttribute(mma_gemm<0,1>, cudaFuncAttributeMaxDynamicSharedMemorySize, GEMM_DSMEM);
    cudaFuncSetAttribute(mma_gemm<1,1>, cudaFuncAttributeMaxDynamicSharedMemorySize, GEMM_DSMEM);

    static int nPersist = 0;
    if (nPersist == 0) {
        int nsm = 148;
        cudaDeviceGetAttribute(&nsm, cudaDevAttrMultiProcessorCount, 0);
        nPersist = 2 * nsm;
    }

    const int SD  = S_ * D_;
    const int SS  = S_ * S_;
    const int SD3 = S_ * 3 * D_;
    const float inv_sqrt_d = 0.03125f;
    dim3 tb(256);

    // launch 1: fused prep (round X, concat bias, all weight transposes)
    prep_kernel<<<PREP_BLOCKS, 256>>>(X, xr, bq, bk, bv, bqkv,
                                      Wq, Wk, Wv, wqkv, W1, wt1, W2, wt2, Wo, wto);

    // launch 2: fused QKV GEMM [8192,1024]x[3072,1024]^T  (tiles: 24 x 64)
    mma_gemm<0,1><<<nPersist, 128, GEMM_DSMEM>>>(
        xr, wqkv, bqkv, qkv, D_, D_, D_, 3*D_, 0, 0, 0, 1.f,
        3*D_/128, BS_/128, 1);

    const __half* q = qkv;
    const __half* k = qkv + D_;
    const __half* v = qkv + 2 * D_;

    // launch 3: V^T per batch: [S, 3072-strided] -> [D,S]
    transpose_h_kernel<<<dim3(D_/64, S_/64, B_), tb>>>(v, vt, 3*D_, S_, SD3, SD);

    // launch 4 (ncu captures ~here): scores = Q @ K^T / sqrt(D)  (fp32 out; tiles 16x16x4)
    mma_gemm<0,0><<<nPersist, 128, GEMM_DSMEM>>>(
        q, k, nullptr, sc, D_, 3*D_, 3*D_, S_, SD3, SD3, SS, inv_sqrt_d,
        S_/128, S_/128, B_);

    // launch 5: attn = fp16(softmax(scores) + intensity)
    softmax_bias_kernel<<<BS_, 256>>>(sc, inten, attn);

    // launch 6: attn_out = attn @ V  (B = vt [D,S]), fp16 out (tiles 8x16x4)
    mma_gemm<0,1><<<nPersist, 128, GEMM_DSMEM>>>(
        attn, vt, nullptr, ao, S_, S_, S_, D_, SS, SD, SD, 1.f,
        D_/128, S_/128, B_);

    // launch 7: O projection (fp32 out; tiles 8x64)
    mma_gemm<0,0><<<nPersist, 128, GEMM_DSMEM>>>(
        ao, wto, bo, tmp, D_, D_, D_, D_, 0, 0, 0, 1.f,
        D_/128, BS_/128, 1);

    // launch 8: h = LN(o + X); hr = fp16(h)
    residual_ln_kernel<1><<<BS_, 256>>>(tmp, X, g1, be1, h, hr);

    // launch 9: FFN1: leaky(h @ W1 + b1), fp16 out (tiles 32x64)
    mma_gemm<1,1><<<nPersist, 128, GEMM_DSMEM>>>(
        hr, wt1, b1, mid, D_, D_, D_, DFF_, 0, 0, 0, 1.f,
        DFF_/128, BS_/128, 1);

    // launch 10: FFN2 (fp32 out; tiles 8x64)
    mma_gemm<0,0><<<nPersist, 128, GEMM_DSMEM>>>(
        mid, wt2, b2, tmp, DFF_, DFF_, DFF_, D_, 0, 0, 0, 1.f,
        D_/128, BS_/128, 1);

    // launch 11: out = LN(ffn + h)
    residual_ln_kernel<0><<<BS_, 256>>>(tmp, h, g2, be2, out, nullptr);
}

// round 15
// speedup vs baseline: 1.0521x; 1.0521x over previous
#include <cuda_runtime.h>
#include <cuda_fp16.h>
#include <cstdint>

#define D_    1024
#define DFF_  4096
#define B_    4
#define S_    2048
#define BS_   (B_ * S_)        // 8192 rows
#define EPS_  1e-6f
#define SLOPE_ 0.01f

// ---------------- scratch (device globals; no allocation allowed) ----------------
__device__ __half g_xr  [BS_ * D_];                 // rounded X (QKV A-operand)
__device__ __half g_qkv [(long long)BS_ * 3 * D_];  // fused QKV output [8192, 3072]
__device__ __half g_vt  [BS_ * D_];                 // V^T per batch [D,S]
__device__ float  g_sc  [(long long)B_ * S_ * S_];  // scores (fp32)
__device__ __half g_attn[(long long)B_ * S_ * S_];  // softmax+intensity (fp16)
__device__ __half g_ao  [BS_ * D_];
__device__ float  g_h   [BS_ * D_];
__device__ __half g_hr  [BS_ * D_];                 // rounded h (FFN1 A-operand)
__device__ __half g_mid [(long long)BS_ * DFF_];
__device__ __half g_tmph[BS_ * D_];                 // O-proj out / FFN2 out (fp16)
__device__ __half g_wqkv[3 * D_ * D_];              // [3072, 1024] transposed fp16
__device__ __half g_wto [D_ * D_];
__device__ __half g_wt1 [(long long)D_ * DFF_];     // W1^T : [DFF, D]
__device__ __half g_wt2 [(long long)D_ * DFF_];     // W2^T : [D, DFF]
__device__ float  g_bqkv[3 * D_];                   // concat bias (fp32)

// ---------------- PTX helpers (portable ISA only) ----------------
__device__ __forceinline__ uint32_t smem_to_u32(const void* smem_ptr) {
    uint32_t addr;
    asm("{ .reg .u64 tmp; cvta.to.shared.u64 tmp, %1; cvt.u32.u64 %0, tmp; }"
        : "=r"(addr) : "l"(smem_ptr));
    return addr;
}

#define CP_ASYNC16(saddr, gptr) \
    asm volatile("cp.async.cg.shared.global [%0], [%1], 16;" :: "r"(saddr), "l"(gptr))
#define CP_COMMIT() asm volatile("cp.async.commit_group;" ::: "memory")
#define CP_WAIT(n)  asm volatile("cp.async.wait_group %0;" :: "n"(n) : "memory")

#define LDSM_X4(r0, r1, r2, r3, addr) \
    asm volatile("ldmatrix.sync.aligned.m8n8.x4.shared.b16 {%0,%1,%2,%3}, [%4];" \
        : "=r"(r0), "=r"(r1), "=r"(r2), "=r"(r3) : "r"(addr))

__device__ __forceinline__ void mma_fp16(float* c, const uint32_t* a, const uint32_t* b) {
    asm volatile(
        "mma.sync.aligned.m16n8k16.row.col.f32.f16.f16.f32 "
        "{%0,%1,%2,%3}, {%4,%5,%6,%7}, {%8,%9}, {%0,%1,%2,%3};"
        : "+f"(c[0]), "+f"(c[1]), "+f"(c[2]), "+f"(c[3])
        : "r"(a[0]), "r"(a[1]), "r"(a[2]), "r"(a[3]), "r"(b[0]), "r"(b[1]));
}

// ---------------- block reductions ----------------
__device__ __forceinline__ float warpRedMax(float v) {
    #pragma unroll
    for (int o = 16; o > 0; o >>= 1) v = fmaxf(v, __shfl_xor_sync(0xffffffffu, v, o));
    return v;
}
__device__ __forceinline__ float warpRedSum(float v) {
    #pragma unroll
    for (int o = 16; o > 0; o >>= 1) v += __shfl_xor_sync(0xffffffffu, v, o);
    return v;
}
__device__ float blockRedMax(float v) {
    __shared__ float sh[8];
    int lane = threadIdx.x & 31, wid = threadIdx.x >> 5;
    __syncthreads();
    v = warpRedMax(v);
    if (lane == 0) sh[wid] = v;
    __syncthreads();
    float r = sh[0];
    #pragma unroll
    for (int i = 1; i < 8; i++) r = fmaxf(r, sh[i]);
    return r;
}
__device__ float blockRedSum(float v) {
    __shared__ float sh[8];
    int lane = threadIdx.x & 31, wid = threadIdx.x >> 5;
    __syncthreads();
    v = warpRedSum(v);
    if (lane == 0) sh[wid] = v;
    __syncthreads();
    float r = 0.f;
    #pragma unroll
    for (int i = 0; i < 8; i++) r += sh[i];
    return r;
}

// ================= fp16 mma.sync GEMM (f32 accumulate) =================
// C[M,N](+z*sC) = act( alpha * A[M,K] @ Bt[N,K]^T + bias )
// 128x128 CTA tile, BK=64 halfs, 128 threads, 4 warps (2m x 2n), warp tile 64x64.
// 3-stage cp.async pipeline, SW128 swizzle, ldmatrix loads.
#define STAGES 3
#define TILE_BYTES  (128 * 128)               // 16 KB (128 rows x 128 bytes)
#define STAGE_BYTES (2 * TILE_BYTES)          // 32 KB
#define GEMM_DSMEM  (STAGES * STAGE_BYTES + 1024)

__device__ __forceinline__ void load_chunk64(
    uint32_t sA_base, uint32_t sB_base,
    const __half* __restrict__ gA, const __half* __restrict__ gB,
    int lda, int ldb, int tid)
{
    #pragma unroll
    for (int j = 0; j < 8; j++) {
        int idx = j * 128 + tid;          // 0..1023 : 16B segments of a 16KB tile
        int row = idx >> 3;
        int seg = idx & 7;
        uint32_t off = (uint32_t)idx * 16u;
        uint32_t sw = off ^ ((off >> 3) & 0x70u);
        const __half* ga = gA + row * lda + seg * 8;
        const __half* gb = gB + row * ldb + seg * 8;
        CP_ASYNC16(sA_base + sw, ga);
        CP_ASYNC16(sB_base + sw, gb);
    }
}

template<int ACT, int OUTH>
__global__ __launch_bounds__(128, 2)
void mma_gemm(const __half* __restrict__ A, const __half* __restrict__ Bt,
              const float* __restrict__ bias, void* __restrict__ Cv,
              int K, int lda, int ldb, int ldc,
              int sA, int sB, int sC, float alpha)
{
    extern __shared__ char smem_raw[];
    uint32_t smem_base = (smem_to_u32(smem_raw) + 1023u) & ~1023u;

    const int z = blockIdx.z;
    const int bm = blockIdx.y * 128;
    const int bn = blockIdx.x * 128;
    const int tid  = threadIdx.x;
    const int lane = tid & 31;
    const int wid  = tid >> 5;
    const int wm = wid >> 1;            // 0..1 : 64-row slab
    const int wn = wid & 1;             // 0..1 : 64-col slab
    const int NK = K >> 6;              // BK = 64 halfs

    // ---- ldmatrix per-thread swizzled base byte offsets (tile-relative) ----
    const int g   = lane >> 3;
    const int rin = lane & 7;
    const int arow_off = ((g & 1) << 3) + rin;
    const int acol_b   = (g >> 1) << 4;
    uint32_t aswb[4];
    #pragma unroll
    for (int mf = 0; mf < 4; mf++) {
        int row = wm * 64 + mf * 16 + arow_off;
        uint32_t off = (uint32_t)row * 128u + (uint32_t)acol_b;
        aswb[mf] = off ^ (((uint32_t)row & 7u) << 4);
    }
    const int brow_off = ((g >> 1) << 3) + rin;
    const int bcol_b   = (g & 1) << 4;
    uint32_t bswb[4];
    #pragma unroll
    for (int p = 0; p < 4; p++) {
        int nrow = wn * 64 + p * 16 + brow_off;
        uint32_t off = (uint32_t)nrow * 128u + (uint32_t)bcol_b;
        bswb[p] = off ^ (((uint32_t)nrow & 7u) << 4);
    }

    float c[4][8][4];
    #pragma unroll
    for (int i = 0; i < 4; i++)
        #pragma unroll
        for (int j = 0; j < 8; j++)
            #pragma unroll
            for (int r = 0; r < 4; r++) c[i][j][r] = 0.f;

    const __half* gA0 = A  + z * sA + bm * lda;
    const __half* gB0 = Bt + z * sB + bn * ldb;

    // prologue
    #pragma unroll
    for (int s = 0; s < STAGES - 1; s++) {
        uint32_t sa = smem_base + s * STAGE_BYTES;
        load_chunk64(sa, sa + TILE_BYTES, gA0 + s * 64, gB0 + s * 64, lda, ldb, tid);
        CP_COMMIT();
    }

    for (int kt = 0; kt < NK; kt++) {
        const int s = kt % STAGES;
        CP_WAIT(STAGES - 2);
        __syncthreads();

        const int ktn = kt + STAGES - 1;
        if (ktn < NK) {
            const int sn = ktn % STAGES;
            uint32_t sa = smem_base + sn * STAGE_BYTES;
            load_chunk64(sa, sa + TILE_BYTES, gA0 + ktn * 64, gB0 + ktn * 64,
                         lda, ldb, tid);
        }
        CP_COMMIT();

        const uint32_t sAb = smem_base + s * STAGE_BYTES;
        const uint32_t sBb = sAb + TILE_BYTES;
        #pragma unroll
        for (int ks = 0; ks < 4; ks++) {     // 4 x k16 = BK 64
            uint32_t a[4][4];
            uint32_t bb[4][4];
            #pragma unroll
            for (int mf = 0; mf < 4; mf++)
                LDSM_X4(a[mf][0], a[mf][1], a[mf][2], a[mf][3], sAb + (aswb[mf] ^ (ks << 5)));
            #pragma unroll
            for (int p = 0; p < 4; p++)
                LDSM_X4(bb[p][0], bb[p][1], bb[p][2], bb[p][3], sBb + (bswb[p] ^ (ks << 5)));
            #pragma unroll
            for (int mf = 0; mf < 4; mf++)
                #pragma unroll
                for (int nf = 0; nf < 8; nf++)
                    mma_fp16(c[mf][nf], a[mf], &bb[nf >> 1][(nf & 1) * 2]);
        }
    }

    // ---- epilogue ----
    float*  Cf = (float*)Cv  + sC * z;
    __half* Ch = (__half*)Cv + sC * z;
    const int r0base = bm + wm * 64 + (lane >> 2);
    const int c0base = bn + wn * 64 + (lane & 3) * 2;
    #pragma unroll
    for (int mf = 0; mf < 4; mf++) {
        #pragma unroll
        for (int nf = 0; nf < 8; nf++) {
            int col = c0base + nf * 8;
            float bx = 0.f, by = 0.f;
            if (bias != nullptr) { bx = bias[col]; by = bias[col + 1]; }
            #pragma unroll
            for (int half_ = 0; half_ < 2; half_++) {
                int row = r0base + mf * 16 + half_ * 8;
                float vx = c[mf][nf][half_ * 2 + 0] * alpha + bx;
                float vy = c[mf][nf][half_ * 2 + 1] * alpha + by;
                if (ACT == 1) {
                    vx = vx > 0.f ? vx : SLOPE_ * vx;
                    vy = vy > 0.f ? vy : SLOPE_ * vy;
                }
                if (OUTH == 1) {
                    *(__half2*)&Ch[row * ldc + col] = __floats2half2_rn(vx, vy);
                } else {
                    *(float2*)&Cf[row * ldc + col] = make_float2(vx, vy);
                }
            }
        }
    }
}

// ================= fused prep kernel =================
#define P_X0   0
#define P_B0   8192
#define P_T30  8195
#define P_W10  11267
#define P_W20  15363
#define P_WO0  19459
#define PREP_BLOCKS 20483

__device__ __forceinline__ void tr_tile(const float* __restrict__ in, __half* __restrict__ out,
                                        int ldIn, int ldOut, int r0, int c0)
{
    __shared__ float t[32][33];
    const int tx = threadIdx.x & 31;
    const int ty = threadIdx.x >> 5;
    #pragma unroll
    for (int j = 0; j < 4; j++)
        t[ty + j * 8][tx] = in[(long long)(r0 + ty + j * 8) * ldIn + c0 + tx];
    __syncthreads();
    #pragma unroll
    for (int j = 0; j < 4; j++)
        out[(long long)(c0 + ty + j * 8) * ldOut + r0 + tx] = __float2half(t[tx][ty + j * 8]);
}

__global__ __launch_bounds__(256)
void prep_kernel(const float* __restrict__ X, __half* __restrict__ xr,
                 const float* __restrict__ bq, const float* __restrict__ bk,
                 const float* __restrict__ bv, float* __restrict__ bqkv,
                 const float* __restrict__ Wq, const float* __restrict__ Wk,
                 const float* __restrict__ Wv, __half* __restrict__ wqkv,
                 const float* __restrict__ W1, __half* __restrict__ wt1,
                 const float* __restrict__ W2, __half* __restrict__ wt2,
                 const float* __restrict__ Wo, __half* __restrict__ wto)
{
    const int b = blockIdx.x;
    if (b < P_B0) {
        int i = b * 256 + threadIdx.x;
        float4 v = ((const float4*)X)[i];
        __half2* o = (__half2*)(xr + 4 * (long long)i);
        o[0] = __floats2half2_rn(v.x, v.y);
        o[1] = __floats2half2_rn(v.z, v.w);
    } else if (b < P_T30) {
        int zz = b - P_B0;
        const float* src = (zz == 0) ? bq : (zz == 1) ? bk : bv;
        #pragma unroll
        for (int j = 0; j < 4; j++)
            bqkv[zz * D_ + threadIdx.x + j * 256] = src[threadIdx.x + j * 256];
    } else if (b < P_W10) {
        int id = b - P_T30;
        int z = id >> 10;            // 0..2
        int rem = id & 1023;
        const float* in = (z == 0) ? Wq : (z == 1) ? Wk : Wv;
        tr_tile(in, wqkv + (long long)z * D_ * D_, D_, D_,
                (rem >> 5) * 32, (rem & 31) * 32);
    } else if (b < P_W20) {
        int id = b - P_W10;          // W1 [D, DFF] -> wt1 [DFF, D]
        tr_tile(W1, wt1, DFF_, D_, (id >> 7) * 32, (id & 127) * 32);
    } else if (b < P_WO0) {
        int id = b - P_W20;          // W2 [DFF, D] -> wt2 [D, DFF]
        tr_tile(W2, wt2, D_, DFF_, (id >> 5) * 32, (id & 31) * 32);
    } else {
        int id = b - P_WO0;          // Wo [D, D] -> wto [D, D]
        tr_tile(Wo, wto, D_, D_, (id >> 5) * 32, (id & 31) * 32);
    }
}

// ---------------- half transpose (V -> V^T per batch), 64x64 tiles, half2 I/O ----------------
__global__ __launch_bounds__(256)
void transpose_h_kernel(const __half* __restrict__ in, __half* __restrict__ out,
                        int ldIn, int ldOut, long long sIn, long long sOut)
{
    __shared__ __half t[64][65];
    const int z = blockIdx.z;
    in  += (long long)z * sIn;
    out += (long long)z * sOut;
    const int c0 = blockIdx.x * 64;
    const int r0 = blockIdx.y * 64;
    const int tx = threadIdx.x & 31;      // half2 col 0..31
    const int ty = threadIdx.x >> 5;      // 0..7
    #pragma unroll
    for (int j = 0; j < 8; j++) {
        int row = ty + j * 8;
        __half2 v = *(const __half2*)&in[(long long)(r0 + row) * ldIn + c0 + 2 * tx];
        t[row][2 * tx]     = __low2half(v);
        t[row][2 * tx + 1] = __high2half(v);
    }
    __syncthreads();
    #pragma unroll
    for (int j = 0; j < 8; j++) {
        int orow = ty + j * 8;            // output row = source col
        __half2 o = __halves2half2(t[2 * tx][orow], t[2 * tx + 1][orow]);
        *(__half2*)&out[(long long)(c0 + orow) * ldOut + r0 + 2 * tx] = o;
    }
}

// ---------------- softmax over last dim (S) + intensity add -> fp16 (vectorized) ----------------
__global__ __launch_bounds__(256)
void softmax_bias_kernel(const float* __restrict__ sc, const float* __restrict__ inten,
                         __half* __restrict__ out)
{
    long long row = blockIdx.x;
    const float4* s4 = (const float4*)(sc    + row * (long long)S_);
    const float4* i4 = (const float4*)(inten + row * (long long)S_);
    __half2*     o2  = (__half2*)     (out   + row * (long long)S_);
    int tid = threadIdx.x;

    float4 va = s4[tid];
    float4 vb = s4[tid + 256];
    float m = fmaxf(fmaxf(fmaxf(va.x, va.y), fmaxf(va.z, va.w)),
                    fmaxf(fmaxf(vb.x, vb.y), fmaxf(vb.z, vb.w)));
    m = blockRedMax(m);

    va.x = __expf(va.x - m); va.y = __expf(va.y - m);
    va.z = __expf(va.z - m); va.w = __expf(va.w - m);
    vb.x = __expf(vb.x - m); vb.y = __expf(vb.y - m);
    vb.z = __expf(vb.z - m); vb.w = __expf(vb.w - m);
    float sum = (va.x + va.y + va.z + va.w) + (vb.x + vb.y + vb.z + vb.w);
    sum = blockRedSum(sum);
    float inv = 1.f / sum;

    float4 ia = i4[tid];
    float4 ib = i4[tid + 256];
    o2[2 * tid]       = __floats2half2_rn(fmaf(va.x, inv, ia.x), fmaf(va.y, inv, ia.y));
    o2[2 * tid + 1]   = __floats2half2_rn(fmaf(va.z, inv, ia.z), fmaf(va.w, inv, ia.w));
    o2[512 + 2 * tid]     = __floats2half2_rn(fmaf(vb.x, inv, ib.x), fmaf(vb.y, inv, ib.y));
    o2[512 + 2 * tid + 1] = __floats2half2_rn(fmaf(vb.z, inv, ib.z), fmaf(vb.w, inv, ib.w));
}

// ---------------- residual + layernorm: a (fp16) + b (fp32) ----------------
template<int WR>
__global__ __launch_bounds__(256)
void residual_ln_kernel(const __half* __restrict__ a, const float* __restrict__ b,
                        const float* __restrict__ g, const float* __restrict__ be,
                        float* __restrict__ out, __half* __restrict__ outr)
{
    long long row = blockIdx.x;
    int tid = threadIdx.x;
    const __half2* pa = (const __half2*)(a + row * (long long)D_ + 4 * tid);
    const float4*  pb = (const float4*)(b + row * (long long)D_);
    __half2 a0 = pa[0];
    __half2 a1 = pa[1];
    float4 y = pb[tid];
    float4 x;
    x.x = __low2float(a0)  + y.x;
    x.y = __high2float(a0) + y.y;
    x.z = __low2float(a1)  + y.z;
    x.w = __high2float(a1) + y.w;

    float s  = x.x + x.y + x.z + x.w;
    float ss = x.x * x.x + x.y * x.y + x.z * x.z + x.w * x.w;
    s  = blockRedSum(s);
    ss = blockRedSum(ss);
    float mu  = s * (1.f / D_);
    float var = ss * (1.f / D_) - mu * mu;
    float r   = rsqrtf(var + EPS_);

    float4 gg = ((const float4*)g)[tid];
    float4 bb = ((const float4*)be)[tid];
    float4 o;
    o.x = (x.x - mu) * r * gg.x + bb.x;
    o.y = (x.y - mu) * r * gg.y + bb.y;
    o.z = (x.z - mu) * r * gg.z + bb.z;
    o.w = (x.w - mu) * r * gg.w + bb.w;
    ((float4*)(out + row * (long long)D_))[tid] = o;
    if (WR) {
        __half2* po = (__half2*)(outr + row * (long long)D_ + 4 * tid);
        po[0] = __floats2half2_rn(o.x, o.y);
        po[1] = __floats2half2_rn(o.z, o.w);
    }
}

// ---------------- launcher ----------------
extern "C" void kernel_launch(void* const* d_in, const int* in_sizes, int n_in,
                              void* d_out, int out_size)
{
    const float* X     = (const float*)d_in[0];
    const float* inten = (const float*)d_in[1];
    const float* Wq = (const float*)d_in[2];  const float* bq = (const float*)d_in[3];
    const float* Wk = (const float*)d_in[4];  const float* bk = (const float*)d_in[5];
    const float* Wv = (const float*)d_in[6];  const float* bv = (const float*)d_in[7];
    const float* Wo = (const float*)d_in[8];  const float* bo = (const float*)d_in[9];
    const float* W1 = (const float*)d_in[10]; const float* b1 = (const float*)d_in[11];
    const float* W2 = (const float*)d_in[12]; const float* b2 = (const float*)d_in[13];
    const float* g1 = (const float*)d_in[14]; const float* be1 = (const float*)d_in[15];
    const float* g2 = (const float*)d_in[16]; const float* be2 = (const float*)d_in[17];
    float* out = (float*)d_out;

    __half *xr, *qkv, *vt, *attn, *ao, *hr, *mid, *tmph;
    __half *wqkv, *wto, *wt1, *wt2;
    float *sc, *h, *bqkv;
    cudaGetSymbolAddress((void**)&xr,   g_xr);
    cudaGetSymbolAddress((void**)&qkv,  g_qkv);
    cudaGetSymbolAddress((void**)&vt,   g_vt);
    cudaGetSymbolAddress((void**)&sc,   g_sc);
    cudaGetSymbolAddress((void**)&attn, g_attn);
    cudaGetSymbolAddress((void**)&ao,   g_ao);
    cudaGetSymbolAddress((void**)&h,    g_h);
    cudaGetSymbolAddress((void**)&hr,   g_hr);
    cudaGetSymbolAddress((void**)&mid,  g_mid);
    cudaGetSymbolAddress((void**)&tmph, g_tmph);
    cudaGetSymbolAddress((void**)&wqkv, g_wqkv);
    cudaGetSymbolAddress((void**)&wto,  g_wto);
    cudaGetSymbolAddress((void**)&wt1,  g_wt1);
    cudaGetSymbolAddress((void**)&wt2,  g_wt2);
    cudaGetSymbolAddress((void**)&bqkv, g_bqkv);

    cudaFuncSetAttribute(mma_gemm<0,0>, cudaFuncAttributeMaxDynamicSharedMemorySize, GEMM_DSMEM);
    cudaFuncSetAttribute(mma_gemm<0,1>, cudaFuncAttributeMaxDynamicSharedMemorySize, GEMM_DSMEM);
    cudaFuncSetAttribute(mma_gemm<1,1>, cudaFuncAttributeMaxDynamicSharedMemorySize, GEMM_DSMEM);

    const int SD  = S_ * D_;
    const int SS  = S_ * S_;
    const int SD3 = S_ * 3 * D_;
    const float inv_sqrt_d = 0.03125f;
    dim3 tb(256);

    // launch 1: fused prep (round X, concat bias, all weight transposes)
    prep_kernel<<<PREP_BLOCKS, 256>>>(X, xr, bq, bk, bv, bqkv,
                                      Wq, Wk, Wv, wqkv, W1, wt1, W2, wt2, Wo, wto);

    // launch 2: fused QKV GEMM [8192,1024]x[3072,1024]^T
    mma_gemm<0,1><<<dim3(3*D_/128, BS_/128, 1), 128, GEMM_DSMEM>>>(
        xr, wqkv, bqkv, qkv, D_, D_, D_, 3*D_, 0, 0, 0, 1.f);

    const __half* q = qkv;
    const __half* k = qkv + D_;
    const __half* v = qkv + 2 * D_;

    // launch 3: V^T per batch: [S, 3072-strided] -> [D,S]
    transpose_h_kernel<<<dim3(D_/64, S_/64, B_), tb>>>(v, vt, 3*D_, S_, SD3, SD);

    // launch 4 (ncu captures ~here): scores = Q @ K^T / sqrt(D)  (fp32 out)
    mma_gemm<0,0><<<dim3(S_/128, S_/128, B_), 128, GEMM_DSMEM>>>(
        q, k, nullptr, sc, D_, 3*D_, 3*D_, S_, SD3, SD3, SS, inv_sqrt_d);

    // launch 5: attn = fp16(softmax(scores) + intensity)
    softmax_bias_kernel<<<BS_, 256>>>(sc, inten, attn);

    // launch 6: attn_out = attn @ V  (B = vt [D,S]), fp16 out
    mma_gemm<0,1><<<dim3(D_/128, S_/128, B_), 128, GEMM_DSMEM>>>(
        attn, vt, nullptr, ao, S_, S_, S_, D_, SS, SD, SD, 1.f);

    // launch 7: O projection (fp16 out)
    mma_gemm<0,1><<<dim3(D_/128, BS_/128, 1), 128, GEMM_DSMEM>>>(
        ao, wto, bo, tmph, D_, D_, D_, D_, 0, 0, 0, 1.f);

    // launch 8: h = LN(o + X); hr = fp16(h)
    residual_ln_kernel<1><<<BS_, 256>>>(tmph, X, g1, be1, h, hr);

    // launch 9: FFN1: leaky(h @ W1 + b1), fp16 out
    mma_gemm<1,1><<<dim3(DFF_/128, BS_/128, 1), 128, GEMM_DSMEM>>>(
        hr, wt1, b1, mid, D_, D_, D_, DFF_, 0, 0, 0, 1.f);

    // launch 10: FFN2 (fp16 out)
    mma_gemm<0,1><<<dim3(D_/128, BS_/128, 1), 128, GEMM_DSMEM>>>(
        mid, wt2, b2, tmph, DFF_, DFF_, DFF_, D_, 0, 0, 0, 1.f);

    // launch 11: out = LN(ffn + h)
    residual_ln_kernel<0><<<BS_, 256>>>(tmph, h, g2, be2, out, nullptr);
}